// round 16
// baseline (speedup 1.0000x reference)
#include <cuda_runtime.h>
#include <math.h>
#include <float.h>

// Problem constants (fixed by the dataset)
#define BB 1024
#define LL 81
#define HH 8
#define DD 64
#define UU 10
#define NSAMP 41
#define WS 9
#define QSTR 68
#define KSTR 68

#define NT1 256

// Kernel-1 shared memory (floats): Qs 5508 | Ks 5508 | bias 292 | pmx 924 | psm 924
// + topi 16 ints
#define BIAS_PAD 292
#define SM1_FLOATS (81*QSTR + 81*KSTR + BIAS_PAD + 924 + 924)
#define SM1_BYTES  (SM1_FLOATS*4 + 16*4)

// Inter-kernel scratch (static device arrays — allowed)
__device__ int   g_topi[BB * HH * UU];
__device__ float g_attn[(size_t)BB * HH * UU * LL];

__device__ __forceinline__ unsigned long long ffma2(unsigned long long a,
                                                    unsigned long long b,
                                                    unsigned long long c) {
    unsigned long long d;
    asm("fma.rn.f32x2 %0, %1, %2, %3;" : "=l"(d) : "l"(a), "l"(b), "l"(c));
    return d;
}
__device__ __forceinline__ float f2sum(unsigned long long a) {
    return __uint_as_float((unsigned)(a & 0xffffffffull)) +
           __uint_as_float((unsigned)(a >> 32));
}
__device__ __forceinline__ void stcs(float* p, float v) {
    asm volatile("st.global.cs.f32 [%0], %1;" :: "l"(p), "f"(v) : "memory");
}

// ============================================================================
// Kernel 1: sampled sparsity measure, top-10 selection, scores+softmax.
// (unchanged from R15 — verified 232 us component)
// ============================================================================
__global__ __launch_bounds__(NT1, 4)
void pa_select_kernel(const float* __restrict__ q_in,
                      const float* __restrict__ k_in,
                      const float* __restrict__ bias_in,
                      float* __restrict__ out_attn)
{
    extern __shared__ float sm[];
    float* Qs    = sm;
    float* Ks    = Qs + 81*QSTR;
    float* biass = Ks + 81*KSTR;
    float* pmx   = biass + BIAS_PAD;
    float* psm   = pmx + 924;
    int*   topi  = (int*)(psm + 924);

    const int tid  = threadIdx.x;
    const int warp = tid >> 5;
    const int lane = tid & 31;

    const int task = blockIdx.x;
    const int b = task >> 3;
    const int h = task & 7;

    const size_t base = ((size_t)b * LL * HH + h) * DD;
    const float* qb = q_in + base;
    const float* kb = k_in + base;

    // ---- Phase A: load Q/K tiles (coalesced float4) + bias ----
    for (int idx = tid; idx < LL * 16; idx += NT1) {
        int row = idx >> 4;
        int vec = idx & 15;
        size_t goff = (size_t)row * (HH * DD) + vec * 4;
        float4 qv = *(const float4*)(qb + goff);
        float4 kv = *(const float4*)(kb + goff);
        *(float4*)(Qs + row*QSTR + vec*4) = qv;
        *(float4*)(Ks + row*KSTR + vec*4) = kv;
    }
    for (int i = tid; i < 289; i += NT1) biass[i] = bias_in[i];
    __syncthreads();

    // ---- Phase B: sampled scores, 4q x 4s per thread, packed f32x2 FMA ----
    if (tid < 231) {
        const int st = tid / 21;        // 0..10
        const int qt = tid - st * 21;   // 0..20

        const float* Qr[4];
        const float* Kr[4];
        #pragma unroll
        for (int i = 0; i < 4; i++) {
            int q = qt + 21 * i; if (q > 80) q = 80;
            Qr[i] = Qs + q * QSTR;
        }
        #pragma unroll
        for (int j = 0; j < 4; j++) {
            int s = st + 11 * j; if (s > 40) s = 40;
            Kr[j] = Ks + (2 * s) * KSTR;
        }

        unsigned long long acc2[4][4];
        #pragma unroll
        for (int i = 0; i < 4; i++)
            #pragma unroll
            for (int j = 0; j < 4; j++) acc2[i][j] = 0ull;

        #pragma unroll 2
        for (int d = 0; d < DD; d += 4) {
            ulonglong2 qv[4];
            #pragma unroll
            for (int i = 0; i < 4; i++) qv[i] = *(const ulonglong2*)(Qr[i] + d);
            #pragma unroll
            for (int j = 0; j < 4; j++) {
                ulonglong2 kv = *(const ulonglong2*)(Kr[j] + d);
                #pragma unroll
                for (int i = 0; i < 4; i++) {
                    acc2[i][j] = ffma2(qv[i].x, kv.x, acc2[i][j]);
                    acc2[i][j] = ffma2(qv[i].y, kv.y, acc2[i][j]);
                }
            }
        }

        #pragma unroll
        for (int i = 0; i < 4; i++) {
            int q = qt + 21 * i;
            if (q < LL) {
                float mx = -FLT_MAX, smv = 0.0f;
                #pragma unroll
                for (int j = 0; j < 4; j++) {
                    if (st + 11 * j < NSAMP) {
                        float v = f2sum(acc2[i][j]);
                        mx = fmaxf(mx, v);
                        smv += v;
                    }
                }
                pmx[st * 84 + q] = mx;
                psm[st * 84 + q] = smv;
            }
        }
    }
    __syncthreads();

    // ---- Phase C (warp 0): folded M-reduction + top-10 (tie -> lower index) ----
    if (warp == 0) {
        float m0, m1, m2 = -FLT_MAX;
        {
            float mx = -FLT_MAX, smv = 0.0f;
            #pragma unroll
            for (int st = 0; st < 11; st++) {
                mx = fmaxf(mx, pmx[st * 84 + lane]);
                smv += psm[st * 84 + lane];
            }
            m0 = mx - smv * (1.0f / 81.0f);
        }
        {
            float mx = -FLT_MAX, smv = 0.0f;
            #pragma unroll
            for (int st = 0; st < 11; st++) {
                mx = fmaxf(mx, pmx[st * 84 + lane + 32]);
                smv += psm[st * 84 + lane + 32];
            }
            m1 = mx - smv * (1.0f / 81.0f);
        }
        if (lane + 64 < LL) {
            float mx = -FLT_MAX, smv = 0.0f;
            #pragma unroll
            for (int st = 0; st < 11; st++) {
                mx = fmaxf(mx, pmx[st * 84 + lane + 64]);
                smv += psm[st * 84 + lane + 64];
            }
            m2 = mx - smv * (1.0f / 81.0f);
        }

        #pragma unroll
        for (int r = 0; r < UU; r++) {
            float bv = m0; int bi = lane;
            if (m1 > bv) { bv = m1; bi = lane + 32; }
            if (m2 > bv) { bv = m2; bi = lane + 64; }
            #pragma unroll
            for (int o = 16; o > 0; o >>= 1) {
                float ov = __shfl_xor_sync(0xffffffffu, bv, o);
                int   oi = __shfl_xor_sync(0xffffffffu, bi, o);
                if (ov > bv || (ov == bv && oi < bi)) { bv = ov; bi = oi; }
            }
            if (lane == 0) topi[r] = bi;
            if (bi == lane)           m0 = -FLT_MAX;
            else if (bi == lane + 32) m1 = -FLT_MAX;
            else if (bi == lane + 64) m2 = -FLT_MAX;
        }
        __syncwarp();
        if (lane < UU) g_topi[task * UU + lane] = topi[lane];
    }
    __syncthreads();

    // ---- Phase D (warps 0-4): 2 rows per warp — scores + softmax + attn out ----
    const float scale = 0.125f;
    if (warp < 5) {
        const int r0 = 2 * warp, r1 = r0 + 1;
        const float* q0p = Qs + topi[r0] * QSTR;
        const float* q1p = Qs + topi[r1] * QSTR;

        float sc[2][3];
        #pragma unroll
        for (int t = 0; t < 3; t++) {
            int k = lane + t * 32;
            const float* kr = Ks + (k < LL ? k : LL - 1) * KSTR;
            unsigned long long a0 = 0ull, a1 = 0ull;
            #pragma unroll 4
            for (int d = 0; d < DD; d += 4) {
                ulonglong2 kv = *(const ulonglong2*)(kr + d);
                ulonglong2 qa = *(const ulonglong2*)(q0p + d);
                ulonglong2 qc = *(const ulonglong2*)(q1p + d);
                a0 = ffma2(qa.x, kv.x, a0);
                a0 = ffma2(qa.y, kv.y, a0);
                a1 = ffma2(qc.x, kv.x, a1);
                a1 = ffma2(qc.y, kv.y, a1);
            }
            sc[0][t] = f2sum(a0);
            sc[1][t] = f2sum(a1);
        }

        float* ab = (out_attn ? out_attn : g_attn) + (size_t)task * UU * LL;

        #pragma unroll
        for (int p = 0; p < 2; p++) {
            const int r = r0 + p;
            const int ri = r / WS, rj = r % WS;   // bias row indexed by RANK (ref quirk)
            float mx = -FLT_MAX;
            #pragma unroll
            for (int t = 0; t < 3; t++) {
                int k = lane + t * 32;
                if (k < LL) {
                    int ki = k / WS, kj = k - ki * WS;
                    int bidx = (ri - ki + (WS - 1)) * (2 * WS - 1) + (rj - kj + (WS - 1));
                    sc[p][t] = (sc[p][t] + biass[bidx]) * scale;
                } else {
                    sc[p][t] = -FLT_MAX;
                }
                mx = fmaxf(mx, sc[p][t]);
            }
            #pragma unroll
            for (int o = 16; o > 0; o >>= 1)
                mx = fmaxf(mx, __shfl_xor_sync(0xffffffffu, mx, o));

            float sum = 0.0f;
            #pragma unroll
            for (int t = 0; t < 3; t++) {
                int k = lane + t * 32;
                sc[p][t] = (k < LL) ? __expf(sc[p][t] - mx) : 0.0f;
                sum += sc[p][t];
            }
            #pragma unroll
            for (int o = 16; o > 0; o >>= 1)
                sum += __shfl_xor_sync(0xffffffffu, sum, o);
            const float inv = 1.0f / sum;

            float* ao = ab + (size_t)r * LL;
            #pragma unroll
            for (int t = 0; t < 3; t++) {
                int k = lane + t * 32;
                if (k < LL) ao[k] = sc[p][t] * inv;
            }
        }
    }
}

// ============================================================================
// Kernel 2: per-(b,h) context = cumsum(V) with top rows replaced by attn @ V.
// 128 threads = 2 tasks per block (beats the CTA-count occupancy ceiling).
// V streamed from gmem with batched loads (MLP=9); ctx stores streaming (.cs).
// ============================================================================
__global__ __launch_bounds__(128)
void pa_context_kernel(const float* __restrict__ v_in,
                       const float* __restrict__ attn_in,
                       float* __restrict__ out_ctx)
{
    __shared__ float attn_s[2][UU * LL];
    __shared__ int   topi_s[2][UU];
    __shared__ int   rank_s[2][LL];

    const int sub  = threadIdx.x >> 6;     // 0,1: sub-task within block
    const int d    = threadIdx.x & 63;
    const int task = blockIdx.x * 2 + sub;

    const float* ap = (attn_in ? attn_in : g_attn) + (size_t)task * UU * LL;
    for (int i = d; i < UU * LL; i += 64) attn_s[sub][i] = ap[i];
    if (d < UU) topi_s[sub][d] = g_topi[task * UU + d];
    for (int l = d; l < LL; l += 64) rank_s[sub][l] = -1;
    __syncthreads();
    if (d < UU) rank_s[sub][topi_s[sub][d]] = d;
    __syncthreads();

    const int b = task >> 3;
    const int h = task & 7;
    const size_t base = ((size_t)b * LL * HH + h) * DD + d;
    const float* vb = v_in + base;
    float* ob = out_ctx + base;

    float upd[UU];
    #pragma unroll
    for (int r = 0; r < UU; r++) upd[r] = 0.0f;
    float cum = 0.0f;

    // 9 batches of 9: issue 9 independent LDGs before consuming (MLP = 9)
    for (int g = 0; g < 9; g++) {
        float vv[9];
        #pragma unroll
        for (int j = 0; j < 9; j++)
            vv[j] = __ldg(vb + (size_t)(g * 9 + j) * (HH * DD));
        #pragma unroll
        for (int j = 0; j < 9; j++) {
            const int l = g * 9 + j;
            cum += vv[j];
            if (rank_s[sub][l] < 0) stcs(ob + (size_t)l * (HH * DD), cum);
            #pragma unroll
            for (int r = 0; r < UU; r++)
                upd[r] += attn_s[sub][r * LL + l] * vv[j];
        }
    }

    #pragma unroll
    for (int r = 0; r < UU; r++)
        stcs(ob + (size_t)topi_s[sub][r] * (HH * DD), upd[r]);
}

extern "C" void kernel_launch(void* const* d_in, const int* in_sizes, int n_in,
                              void* d_out, int out_size)
{
    const float* q    = (const float*)d_in[0];
    const float* k    = (const float*)d_in[1];
    const float* v    = (const float*)d_in[2];
    const float* bias = (const float*)d_in[3];
    float* out = (float*)d_out;

    const long long ctx_elems  = (long long)BB * LL * HH * DD;
    const long long attn_elems = (long long)BB * HH * UU * LL;
    float* attn_out = ((long long)out_size >= ctx_elems + attn_elems)
                        ? out + ctx_elems : (float*)0;

    cudaFuncSetAttribute(pa_select_kernel,
                         cudaFuncAttributeMaxDynamicSharedMemorySize, SM1_BYTES);
    pa_select_kernel<<<BB * HH, NT1, SM1_BYTES>>>(q, k, bias, attn_out);
    pa_context_kernel<<<BB * HH / 2, 128>>>(v, attn_out, out);
}

// round 17
// speedup vs baseline: 1.0766x; 1.0766x over previous
#include <cuda_runtime.h>
#include <math.h>
#include <float.h>

// Problem constants (fixed by the dataset)
#define BB 1024
#define LL 81
#define HH 8
#define DD 64
#define UU 10
#define NSAMP 41
#define WS 9
#define QSTR 68
#define KSTR 68

#define NT1 256

// Kernel-1 shared memory (floats): Qs 5508 | Ks 5508 | bias 292 | pmx 924 | psm 924
// + topi 16 ints
#define BIAS_PAD 292
#define SM1_FLOATS (81*QSTR + 81*KSTR + BIAS_PAD + 924 + 924)
#define SM1_BYTES  (SM1_FLOATS*4 + 16*4)

// Inter-kernel scratch (static device arrays — allowed)
__device__ int   g_topi[BB * HH * UU];
__device__ float g_attn[(size_t)BB * HH * UU * LL];

__device__ __forceinline__ unsigned long long ffma2(unsigned long long a,
                                                    unsigned long long b,
                                                    unsigned long long c) {
    unsigned long long d;
    asm("fma.rn.f32x2 %0, %1, %2, %3;" : "=l"(d) : "l"(a), "l"(b), "l"(c));
    return d;
}
__device__ __forceinline__ float f2sum(unsigned long long a) {
    return __uint_as_float((unsigned)(a & 0xffffffffull)) +
           __uint_as_float((unsigned)(a >> 32));
}

// ============================================================================
// Kernel 1: sampled sparsity measure, top-10 selection, scores+softmax.
// (byte-identical to R15 — verified 232 us component)
// ============================================================================
__global__ __launch_bounds__(NT1, 4)
void pa_select_kernel(const float* __restrict__ q_in,
                      const float* __restrict__ k_in,
                      const float* __restrict__ bias_in,
                      float* __restrict__ out_attn)
{
    extern __shared__ float sm[];
    float* Qs    = sm;
    float* Ks    = Qs + 81*QSTR;
    float* biass = Ks + 81*KSTR;
    float* pmx   = biass + BIAS_PAD;
    float* psm   = pmx + 924;
    int*   topi  = (int*)(psm + 924);

    const int tid  = threadIdx.x;
    const int warp = tid >> 5;
    const int lane = tid & 31;

    const int task = blockIdx.x;
    const int b = task >> 3;
    const int h = task & 7;

    const size_t base = ((size_t)b * LL * HH + h) * DD;
    const float* qb = q_in + base;
    const float* kb = k_in + base;

    // ---- Phase A: load Q/K tiles (coalesced float4) + bias ----
    for (int idx = tid; idx < LL * 16; idx += NT1) {
        int row = idx >> 4;
        int vec = idx & 15;
        size_t goff = (size_t)row * (HH * DD) + vec * 4;
        float4 qv = *(const float4*)(qb + goff);
        float4 kv = *(const float4*)(kb + goff);
        *(float4*)(Qs + row*QSTR + vec*4) = qv;
        *(float4*)(Ks + row*KSTR + vec*4) = kv;
    }
    for (int i = tid; i < 289; i += NT1) biass[i] = bias_in[i];
    __syncthreads();

    // ---- Phase B: sampled scores, 4q x 4s per thread, packed f32x2 FMA ----
    if (tid < 231) {
        const int st = tid / 21;        // 0..10
        const int qt = tid - st * 21;   // 0..20

        const float* Qr[4];
        const float* Kr[4];
        #pragma unroll
        for (int i = 0; i < 4; i++) {
            int q = qt + 21 * i; if (q > 80) q = 80;
            Qr[i] = Qs + q * QSTR;
        }
        #pragma unroll
        for (int j = 0; j < 4; j++) {
            int s = st + 11 * j; if (s > 40) s = 40;
            Kr[j] = Ks + (2 * s) * KSTR;
        }

        unsigned long long acc2[4][4];
        #pragma unroll
        for (int i = 0; i < 4; i++)
            #pragma unroll
            for (int j = 0; j < 4; j++) acc2[i][j] = 0ull;

        #pragma unroll 2
        for (int d = 0; d < DD; d += 4) {
            ulonglong2 qv[4];
            #pragma unroll
            for (int i = 0; i < 4; i++) qv[i] = *(const ulonglong2*)(Qr[i] + d);
            #pragma unroll
            for (int j = 0; j < 4; j++) {
                ulonglong2 kv = *(const ulonglong2*)(Kr[j] + d);
                #pragma unroll
                for (int i = 0; i < 4; i++) {
                    acc2[i][j] = ffma2(qv[i].x, kv.x, acc2[i][j]);
                    acc2[i][j] = ffma2(qv[i].y, kv.y, acc2[i][j]);
                }
            }
        }

        #pragma unroll
        for (int i = 0; i < 4; i++) {
            int q = qt + 21 * i;
            if (q < LL) {
                float mx = -FLT_MAX, smv = 0.0f;
                #pragma unroll
                for (int j = 0; j < 4; j++) {
                    if (st + 11 * j < NSAMP) {
                        float v = f2sum(acc2[i][j]);
                        mx = fmaxf(mx, v);
                        smv += v;
                    }
                }
                pmx[st * 84 + q] = mx;
                psm[st * 84 + q] = smv;
            }
        }
    }
    __syncthreads();

    // ---- Phase C (warp 0): folded M-reduction + top-10 (tie -> lower index) ----
    if (warp == 0) {
        float m0, m1, m2 = -FLT_MAX;
        {
            float mx = -FLT_MAX, smv = 0.0f;
            #pragma unroll
            for (int st = 0; st < 11; st++) {
                mx = fmaxf(mx, pmx[st * 84 + lane]);
                smv += psm[st * 84 + lane];
            }
            m0 = mx - smv * (1.0f / 81.0f);
        }
        {
            float mx = -FLT_MAX, smv = 0.0f;
            #pragma unroll
            for (int st = 0; st < 11; st++) {
                mx = fmaxf(mx, pmx[st * 84 + lane + 32]);
                smv += psm[st * 84 + lane + 32];
            }
            m1 = mx - smv * (1.0f / 81.0f);
        }
        if (lane + 64 < LL) {
            float mx = -FLT_MAX, smv = 0.0f;
            #pragma unroll
            for (int st = 0; st < 11; st++) {
                mx = fmaxf(mx, pmx[st * 84 + lane + 64]);
                smv += psm[st * 84 + lane + 64];
            }
            m2 = mx - smv * (1.0f / 81.0f);
        }

        #pragma unroll
        for (int r = 0; r < UU; r++) {
            float bv = m0; int bi = lane;
            if (m1 > bv) { bv = m1; bi = lane + 32; }
            if (m2 > bv) { bv = m2; bi = lane + 64; }
            #pragma unroll
            for (int o = 16; o > 0; o >>= 1) {
                float ov = __shfl_xor_sync(0xffffffffu, bv, o);
                int   oi = __shfl_xor_sync(0xffffffffu, bi, o);
                if (ov > bv || (ov == bv && oi < bi)) { bv = ov; bi = oi; }
            }
            if (lane == 0) topi[r] = bi;
            if (bi == lane)           m0 = -FLT_MAX;
            else if (bi == lane + 32) m1 = -FLT_MAX;
            else if (bi == lane + 64) m2 = -FLT_MAX;
        }
        __syncwarp();
        if (lane < UU) g_topi[task * UU + lane] = topi[lane];
    }
    __syncthreads();

    // ---- Phase D (warps 0-4): 2 rows per warp — scores + softmax + attn out ----
    const float scale = 0.125f;
    if (warp < 5) {
        const int r0 = 2 * warp, r1 = r0 + 1;
        const float* q0p = Qs + topi[r0] * QSTR;
        const float* q1p = Qs + topi[r1] * QSTR;

        float sc[2][3];
        #pragma unroll
        for (int t = 0; t < 3; t++) {
            int k = lane + t * 32;
            const float* kr = Ks + (k < LL ? k : LL - 1) * KSTR;
            unsigned long long a0 = 0ull, a1 = 0ull;
            #pragma unroll 4
            for (int d = 0; d < DD; d += 4) {
                ulonglong2 kv = *(const ulonglong2*)(kr + d);
                ulonglong2 qa = *(const ulonglong2*)(q0p + d);
                ulonglong2 qc = *(const ulonglong2*)(q1p + d);
                a0 = ffma2(qa.x, kv.x, a0);
                a0 = ffma2(qa.y, kv.y, a0);
                a1 = ffma2(qc.x, kv.x, a1);
                a1 = ffma2(qc.y, kv.y, a1);
            }
            sc[0][t] = f2sum(a0);
            sc[1][t] = f2sum(a1);
        }

        float* ab = (out_attn ? out_attn : g_attn) + (size_t)task * UU * LL;

        #pragma unroll
        for (int p = 0; p < 2; p++) {
            const int r = r0 + p;
            const int ri = r / WS, rj = r % WS;   // bias row indexed by RANK (ref quirk)
            float mx = -FLT_MAX;
            #pragma unroll
            for (int t = 0; t < 3; t++) {
                int k = lane + t * 32;
                if (k < LL) {
                    int ki = k / WS, kj = k - ki * WS;
                    int bidx = (ri - ki + (WS - 1)) * (2 * WS - 1) + (rj - kj + (WS - 1));
                    sc[p][t] = (sc[p][t] + biass[bidx]) * scale;
                } else {
                    sc[p][t] = -FLT_MAX;
                }
                mx = fmaxf(mx, sc[p][t]);
            }
            #pragma unroll
            for (int o = 16; o > 0; o >>= 1)
                mx = fmaxf(mx, __shfl_xor_sync(0xffffffffu, mx, o));

            float sum = 0.0f;
            #pragma unroll
            for (int t = 0; t < 3; t++) {
                int k = lane + t * 32;
                sc[p][t] = (k < LL) ? __expf(sc[p][t] - mx) : 0.0f;
                sum += sc[p][t];
            }
            #pragma unroll
            for (int o = 16; o > 0; o >>= 1)
                sum += __shfl_xor_sync(0xffffffffu, sum, o);
            const float inv = 1.0f / sum;

            float* ao = ab + (size_t)r * LL;
            #pragma unroll
            for (int t = 0; t < 3; t++) {
                int k = lane + t * 32;
                if (k < LL) ao[k] = sc[p][t] * inv;
            }
        }
    }
}

// ============================================================================
// Kernel 2: per-(b,h) context = cumsum(V) with top rows replaced by attn @ V.
// Warp = task; lane owns a d-pair; float2 V loads (half the instructions,
// full 256B row per warp LDG). Batched loads keep MLP = 9.
// ============================================================================
__global__ __launch_bounds__(64)
void pa_context_kernel(const float* __restrict__ v_in,
                       const float* __restrict__ attn_in,
                       float* __restrict__ out_ctx)
{
    __shared__ float attn_s[2][UU * LL];
    __shared__ int   topi_s[2][UU];
    __shared__ int   rank_s[2][LL];

    const int sub  = threadIdx.x >> 5;     // warp in block = sub-task
    const int lane = threadIdx.x & 31;
    const int task = blockIdx.x * 2 + sub;

    const float* ap = (attn_in ? attn_in : g_attn) + (size_t)task * UU * LL;
    for (int i = lane; i < UU * LL; i += 32) attn_s[sub][i] = ap[i];
    if (lane < UU) topi_s[sub][lane] = g_topi[task * UU + lane];
    for (int l = lane; l < LL; l += 32) rank_s[sub][l] = -1;
    __syncwarp();
    if (lane < UU) rank_s[sub][topi_s[sub][lane]] = lane;
    __syncwarp();

    const int b = task >> 3;
    const int h = task & 7;
    const size_t base = ((size_t)b * LL * HH + h) * DD + 2 * lane;
    const float* vb = v_in + base;
    float* ob = out_ctx + base;

    float2 upd[UU];
    #pragma unroll
    for (int r = 0; r < UU; r++) upd[r] = make_float2(0.f, 0.f);
    float2 cum = make_float2(0.f, 0.f);

    // 9 batches of 9: issue 9 independent float2 LDGs before consuming (MLP=9)
    for (int g = 0; g < 9; g++) {
        float2 vv[9];
        #pragma unroll
        for (int j = 0; j < 9; j++)
            vv[j] = __ldg((const float2*)(vb + (size_t)(g * 9 + j) * (HH * DD)));
        #pragma unroll
        for (int j = 0; j < 9; j++) {
            const int l = g * 9 + j;
            cum.x += vv[j].x;
            cum.y += vv[j].y;
            if (rank_s[sub][l] < 0)
                *(float2*)(ob + (size_t)l * (HH * DD)) = cum;
            #pragma unroll
            for (int r = 0; r < UU; r++) {
                float w = attn_s[sub][r * LL + l];
                upd[r].x += w * vv[j].x;
                upd[r].y += w * vv[j].y;
            }
        }
    }

    #pragma unroll
    for (int r = 0; r < UU; r++)
        *(float2*)(ob + (size_t)topi_s[sub][r] * (HH * DD)) = upd[r];
}

extern "C" void kernel_launch(void* const* d_in, const int* in_sizes, int n_in,
                              void* d_out, int out_size)
{
    const float* q    = (const float*)d_in[0];
    const float* k    = (const float*)d_in[1];
    const float* v    = (const float*)d_in[2];
    const float* bias = (const float*)d_in[3];
    float* out = (float*)d_out;

    const long long ctx_elems  = (long long)BB * LL * HH * DD;
    const long long attn_elems = (long long)BB * HH * UU * LL;
    float* attn_out = ((long long)out_size >= ctx_elems + attn_elems)
                        ? out + ctx_elems : (float*)0;

    cudaFuncSetAttribute(pa_select_kernel,
                         cudaFuncAttributeMaxDynamicSharedMemorySize, SM1_BYTES);
    pa_select_kernel<<<BB * HH, NT1, SM1_BYTES>>>(q, k, bias, attn_out);
    pa_context_kernel<<<BB * HH / 2, 64>>>(v, attn_out, out);
}